// round 15
// baseline (speedup 1.0000x reference)
#include <cuda_runtime.h>
#include <cuda_bf16.h>
#include <cstdint>

// ---------------------------------------------------------------------------
// NaiveAttention on GB300. B=4, N=4096, C=1024 fp32.
// R15: R14 + (a) D0/D1-interleaved MMA dispatch (2 independent accumulator
// chains -> hide tcgen05 dispatch latency), (b) epilogue on all 8 warps,
// (c) prologue loads overlap cluster sync.
// ---------------------------------------------------------------------------

#if !defined(__CUDA_ARCH__)
#define USE_TC 1
#elif defined(__CUDA_ARCH_FEAT_SM103_ALL) || defined(__CUDA_ARCH_FEAT_SM100_ALL) || \
      defined(__CUDA_ARCH_FEAT_SM101_ALL) || defined(__CUDA_ARCH_SPECIFIC__) || \
      defined(__CUDA_ARCH_FAMILY_SPECIFIC__)
#define USE_TC 1
#else
#define USE_TC 0
#endif

#define DIMC 1024
#define NSEQ 4096
#define NB   4

typedef __nv_bfloat16 bf16;

// Scratch (device globals — no allocation allowed).
__device__ bf16  g_xh [16777216], g_xl [16777216];
__device__ bf16  g_wth[4194304],  g_wtl[4194304];
__device__ bf16  g_qh [16777216], g_ql [16777216];
__device__ bf16  g_kh [16777216], g_kl [16777216];
__device__ float g_v  [16777216];
__device__ bf16  g_vth[16777216], g_vtl[16777216];
__device__ bf16  g_ah [67108864], g_al [67108864];   // exp(scores) hi/lo (unnormalized)
__device__ bf16  g_aoh[16777216], g_aol[16777216];
__device__ float g_P  [262144];                       // row partial sums [16384][16]
__device__ float g_rinv[16384];                       // 1/rowsum

#define KT 64
#define BNC 512      // cluster N tile (two 256 halves)
// idesc kind::f16 cg2: dtype=F32(1<<4), a=b=BF16(1<<7|1<<10), N=256(32<<17), M=256(16<<24)
#define IDESC_CG2 0x10400490u
// Stage per CTA: Ahi16K@0 Alo@16K | B0hi@32K B0lo@48K | B1hi@64K B1lo@80K
#define BUF_BYTES 98304
#define NSTAGE 2
#define SMEM_BYTES (2048 + NSTAGE * BUF_BYTES)

// ---- bf16 helpers (legal on base target too) ------------------------------
__device__ __forceinline__ uint32_t pack_bf16(float lo, float hi) {
    uint32_t r;
    asm("cvt.rn.satfinite.bf16x2.f32 %0, %1, %2;" : "=r"(r) : "f"(hi), "f"(lo));
    return r;
}
__device__ __forceinline__ float bf16_rn_f32(float x) {
    uint32_t r;
    asm("cvt.rn.satfinite.bf16x2.f32 %0, %1, %1;" : "=r"(r) : "f"(x));
    return __uint_as_float(r << 16);
}

#if USE_TC
// ---------------------------------------------------------------------------
// sm_103a-only PTX helpers
// ---------------------------------------------------------------------------
__device__ __forceinline__ uint32_t smem_u32(const void* p) {
    uint32_t a;
    asm("{ .reg .u64 t; cvta.to.shared.u64 t, %1; cvt.u32.u64 %0, t; }"
        : "=r"(a) : "l"(p));
    return a;
}

#define MBAR_INIT(addr, cnt) \
    asm volatile("mbarrier.init.shared.b64 [%0], %1;" :: "r"(addr), "r"(cnt) : "memory")

// local wait, cta-scope acquire
#define MBAR_WAIT(addr, ph) do {                                              \
    uint32_t _m = (addr); uint32_t _p = (ph); uint32_t _done;                 \
    asm volatile("{\n\t.reg .pred p;\n\t"                                     \
        "mbarrier.try_wait.parity.acquire.cta.shared::cta.b64 p, [%1], %2;\n\t" \
        "selp.b32 %0, 1, 0, p;\n\t}"                                          \
        : "=r"(_done) : "r"(_m), "r"(_p) : "memory");                         \
    if (!_done) {                                                             \
        asm volatile("{\n\t.reg .pred P1;\n\t"                                \
            "WL_%=:\n\t"                                                      \
            "mbarrier.try_wait.parity.acquire.cta.shared::cta.b64 P1, [%0], %1, 0x989680;\n\t" \
            "@P1 bra.uni WD_%=;\n\t"                                          \
            "bra.uni WL_%=;\n\t"                                              \
            "WD_%=:\n\t}"                                                     \
            :: "r"(_m), "r"(_p) : "memory");                                  \
    }                                                                         \
} while (0)

// local wait, cluster-scope acquire (protects peer-CTA SMEM reads by cg2 MMA)
#define MBAR_WAIT_CL(addr, ph) do {                                           \
    uint32_t _m = (addr); uint32_t _p = (ph); uint32_t _done;                 \
    asm volatile("{\n\t.reg .pred p;\n\t"                                     \
        "mbarrier.try_wait.parity.acquire.cluster.shared::cta.b64 p, [%1], %2;\n\t" \
        "selp.b32 %0, 1, 0, p;\n\t}"                                          \
        : "=r"(_done) : "r"(_m), "r"(_p) : "memory");                         \
    if (!_done) {                                                             \
        asm volatile("{\n\t.reg .pred P1;\n\t"                                \
            "WL_%=:\n\t"                                                      \
            "mbarrier.try_wait.parity.acquire.cluster.shared::cta.b64 P1, [%0], %1, 0x989680;\n\t" \
            "@P1 bra.uni WD_%=;\n\t"                                          \
            "bra.uni WL_%=;\n\t"                                              \
            "WD_%=:\n\t}"                                                     \
            :: "r"(_m), "r"(_p) : "memory");                                  \
    }                                                                         \
} while (0)

// arrive on cluster-rank-0's mbarrier at the same SMEM offset (mapa)
#define MBAR_ARRIVE_R0(addr) \
    asm volatile("{\n\t.reg .b32 ra;\n\t" \
        "mapa.shared::cluster.u32 ra, %0, %1;\n\t" \
        "mbarrier.arrive.shared::cluster.b64 _, [ra];\n\t}" \
        :: "r"(addr), "r"(0) : "memory")

#define CLUSTER_SYNC() do { \
    asm volatile("barrier.cluster.arrive.aligned;" ::: "memory"); \
    asm volatile("barrier.cluster.wait.aligned;" ::: "memory"); \
} while (0)

#define TC_ALLOC_CG2(sm, n)  asm volatile("tcgen05.alloc.cta_group::2.sync.aligned.shared::cta.b32 [%0], %1;" :: "r"(sm), "r"(n) : "memory")
#define TC_DEALLOC_CG2(t, n) asm volatile("tcgen05.dealloc.cta_group::2.sync.aligned.b32 %0, %1;" :: "r"(t), "r"(n))
#define TC_RELINQ_CG2()      asm volatile("tcgen05.relinquish_alloc_permit.cta_group::2.sync.aligned;")
#define TC_COMMIT_MC2(mb)    asm volatile("tcgen05.commit.cta_group::2.mbarrier::arrive::one.shared::cluster.multicast::cluster.b64 [%0], %1;" :: "r"(mb), "h"((uint16_t)0x3) : "memory")
#define TC_FENCE_AFTER()  asm volatile("tcgen05.fence::after_thread_sync;" ::: "memory")
#define TC_FENCE_BEFORE() asm volatile("tcgen05.fence::before_thread_sync;" ::: "memory")
#define TC_WAIT_LD()      asm volatile("tcgen05.wait::ld.sync.aligned;" ::: "memory")
#define FENCE_ASYNC()     asm volatile("fence.proxy.async.shared::cta;" ::: "memory")

#define CP_ASYNC16(sm, gp) \
    asm volatile("cp.async.cg.shared.global [%0], [%1], 16;" :: "r"(sm), "l"(gp) : "memory")
#define CP_COMMIT() asm volatile("cp.async.commit_group;" ::: "memory")
#define CP_WAIT1()  asm volatile("cp.async.wait_group 1;" ::: "memory")

#define TC_LD_X32(r, a) \
    asm volatile("tcgen05.ld.sync.aligned.32x32b.x32.b32 " \
        "{%0, %1, %2, %3, %4, %5, %6, %7, %8, %9, %10, %11, %12, %13, %14, %15, " \
        " %16, %17, %18, %19, %20, %21, %22, %23, %24, %25, %26, %27, %28, %29, %30, %31}, [%32];" \
        : "=r"((r)[0]), "=r"((r)[1]), "=r"((r)[2]), "=r"((r)[3]), \
          "=r"((r)[4]), "=r"((r)[5]), "=r"((r)[6]), "=r"((r)[7]), \
          "=r"((r)[8]), "=r"((r)[9]), "=r"((r)[10]), "=r"((r)[11]), \
          "=r"((r)[12]), "=r"((r)[13]), "=r"((r)[14]), "=r"((r)[15]), \
          "=r"((r)[16]), "=r"((r)[17]), "=r"((r)[18]), "=r"((r)[19]), \
          "=r"((r)[20]), "=r"((r)[21]), "=r"((r)[22]), "=r"((r)[23]), \
          "=r"((r)[24]), "=r"((r)[25]), "=r"((r)[26]), "=r"((r)[27]), \
          "=r"((r)[28]), "=r"((r)[29]), "=r"((r)[30]), "=r"((r)[31]) \
        : "r"(a))

// cg2 bf16 SS MMA (8-register disable-output-lane vector)
__device__ __forceinline__ void mma_f16_ss_cg2(uint32_t d, uint64_t a, uint64_t b,
                                               uint32_t idesc, uint32_t en) {
    asm volatile("{\n\t.reg .pred p;\n\tsetp.ne.u32 p, %4, 0;\n\t"
        "tcgen05.mma.cta_group::2.kind::f16 [%0], %1, %2, %3, "
        "{%5, %5, %5, %5, %5, %5, %5, %5}, p;\n\t}"
        :: "r"(d), "l"(a), "l"(b), "r"(idesc), "r"(en), "r"(0u) : "memory");
}

__device__ __forceinline__ uint64_t mk_desc(uint32_t addr) {
    const uint64_t base = (uint64_t(2) << 61) | (uint64_t(1) << 46)
                        | (uint64_t(64) << 32) | (uint64_t(1) << 16);
    return base | ((uint64_t)(addr >> 4) & 0x3FFF);
}

__device__ __forceinline__ uint32_t sw128(uint32_t off) {
    return off ^ ((off >> 3) & 0x70);
}
#endif  // USE_TC

// ---------------------------------------------------------------------------
// GEMM (2-CTA clusters, 256M x 512N per cluster):
//   C[z] = (Ahi+Alo)[z] @ (Bhi+Blo)[z]^T.
//   OUTM=0: Cf fp32 (+bias).  OUTM=1: Chi/Clo bf16 pair (+bias).
//   OUTM=2: e=exp(escale*acc) -> pair + row partials.  OUTM=3: acc*rinv[row].
//   Grid: x = M/128 (cluster dim 2 on x), y = N/512, z = batch.
//   M % 256 == 0, N % 512 == 0, K % 64 == 0.
// ---------------------------------------------------------------------------
template <int OUTM, bool HAS_BIAS>
__global__ __launch_bounds__(256, 1) __cluster_dims__(2, 1, 1)
void tc_gemm6(const bf16* __restrict__ Ahi, const bf16* __restrict__ Alo,
              const bf16* __restrict__ Bhi, const bf16* __restrict__ Blo,
              const float* __restrict__ bias,
              float* __restrict__ Cf, bf16* __restrict__ Chi, bf16* __restrict__ Clo,
              const float* __restrict__ rinv, float* __restrict__ Prow, float escale,
              int M, int N, int K,
              long long sA, long long sB, long long sC)
{
    extern __shared__ char smem[];

    Ahi += (long long)blockIdx.z * sA;  Alo += (long long)blockIdx.z * sA;
    Bhi += (long long)blockIdx.z * sB;  Blo += (long long)blockIdx.z * sB;

    const int tid  = threadIdx.x;
    const int rank = blockIdx.x & 1;                  // == cluster_ctarank
    const int m0   = blockIdx.x * 128;                // includes rank offset
    const int n0   = blockIdx.y * BNC;                // 512-wide N tile

#if USE_TC
    const uint32_t sb    = smem_u32(smem);
    const uint32_t tiles = (sb + 64 + 1023) & ~1023u;
    char* tilesg = smem + (tiles - sb);
    const uint32_t mbF[NSTAGE] = { sb,      sb + 8  };   // MMA-done (both CTAs)
    const uint32_t mbR[NSTAGE] = { sb + 16, sb + 24 };   // loads-ready (rank0)
    const uint32_t tptr = sb + 32;

    if (tid < 32) TC_ALLOC_CG2(tptr, 512);
    if (tid == 0) {
        MBAR_INIT(mbF[0], 1); MBAR_INIT(mbF[1], 1);
        MBAR_INIT(mbR[0], 2); MBAR_INIT(mbR[1], 2);
    }
    __syncthreads();
    uint32_t tmem;
    asm volatile("ld.shared.b32 %0, [%1];" : "=r"(tmem) : "r"(tptr));

    const int nk = K / KT;
    int phF[NSTAGE] = { 0, 0 };
    int phR = 0, stR = 0;

    // loader geometry: 2 threads per row, 64B half-rows.
    const int lrow  = tid >> 1;          // 0..127
    const int lhalf = tid & 1;
    const long long aoff  = (long long)(m0 + lrow) * K + lhalf * 32;
    const long long boff0 = (long long)(n0 +       rank * 128 + lrow) * K + lhalf * 32;
    const long long boff1 = (long long)(n0 + 256 + rank * 128 + lrow) * K + lhalf * 32;
    const uint32_t soff   = (uint32_t)(lrow * 128 + lhalf * 64);

    auto load_tile = [&](int tt, uint32_t sbase) {
        const long long kof = (long long)tt * KT;
        const bf16* p0 = Ahi + aoff  + kof;
        const bf16* p1 = Alo + aoff  + kof;
        const bf16* p2 = Bhi + boff0 + kof;
        const bf16* p3 = Blo + boff0 + kof;
        const bf16* p4 = Bhi + boff1 + kof;
        const bf16* p5 = Blo + boff1 + kof;
        #pragma unroll
        for (int j = 0; j < 4; j++) CP_ASYNC16(sbase +         sw128(soff + j * 16), p0 + j * 8);
        #pragma unroll
        for (int j = 0; j < 4; j++) CP_ASYNC16(sbase + 16384 + sw128(soff + j * 16), p1 + j * 8);
        #pragma unroll
        for (int j = 0; j < 4; j++) CP_ASYNC16(sbase + 32768 + sw128(soff + j * 16), p2 + j * 8);
        #pragma unroll
        for (int j = 0; j < 4; j++) CP_ASYNC16(sbase + 49152 + sw128(soff + j * 16), p3 + j * 8);
        #pragma unroll
        for (int j = 0; j < 4; j++) CP_ASYNC16(sbase + 65536 + sw128(soff + j * 16), p4 + j * 8);
        #pragma unroll
        for (int j = 0; j < 4; j++) CP_ASYNC16(sbase + 81920 + sw128(soff + j * 16), p5 + j * 8);
    };

    // prologue: tile 0 loads overlap the cluster handshake
    load_tile(0, tiles);
    CP_COMMIT();
    CLUSTER_SYNC();    // mbarriers + TMEM alloc visible cluster-wide

    for (int t = 0; t < nk; t++) {
        const int buf = t & 1;
        const uint32_t sbase = tiles + buf * BUF_BYTES;

        // issue loads for t+1 into the other buffer (gated by MMA-done t-1)
        const int tp = t + 1;
        if (tp < nk) {
            const int nbuf = tp & 1;
            if (tp >= NSTAGE) { MBAR_WAIT(mbF[nbuf], phF[nbuf]); phF[nbuf] ^= 1; }
            load_tile(tp, tiles + nbuf * BUF_BYTES);
        }
        CP_COMMIT();               // keep group count aligned (may be empty)
        CP_WAIT1();                // tile t's loads complete locally
        FENCE_ASYNC();
        __syncthreads();

        // signal: this CTA's stage `buf` ready (arrive on rank0's mbR)
        if (tid == 0) MBAR_ARRIVE_R0(mbR[buf]);

        // rank 0 thread 0: wait both CTAs ready, issue 24 cg2 MMAs.
        // D0/D1 interleaved -> two independent accumulator chains hide
        // tcgen05 dispatch latency.
        if (rank == 0 && tid == 0) {
            MBAR_WAIT_CL(mbR[stR], phR);
            if (++stR == NSTAGE) { stR = 0; phR ^= 1; }
            uint64_t ah = mk_desc(sbase);
            uint64_t al = mk_desc(sbase + 16384);
            uint64_t bh0 = mk_desc(sbase + 32768);
            uint64_t bl0 = mk_desc(sbase + 49152);
            uint64_t bh1 = mk_desc(sbase + 65536);
            uint64_t bl1 = mk_desc(sbase + 81920);
            const uint32_t d0 = tmem, d1 = tmem + 256;
            #pragma unroll
            for (int kc = 0; kc < 4; kc++) {
                const uint32_t en0 = (t | kc) != 0;
                mma_f16_ss_cg2(d0, ah + kc * 2, bh0 + kc * 2, IDESC_CG2, en0);
                mma_f16_ss_cg2(d1, ah + kc * 2, bh1 + kc * 2, IDESC_CG2, en0);
                mma_f16_ss_cg2(d0, ah + kc * 2, bl0 + kc * 2, IDESC_CG2, 1);
                mma_f16_ss_cg2(d1, ah + kc * 2, bl1 + kc * 2, IDESC_CG2, 1);
                mma_f16_ss_cg2(d0, al + kc * 2, bh0 + kc * 2, IDESC_CG2, 1);
                mma_f16_ss_cg2(d1, al + kc * 2, bh1 + kc * 2, IDESC_CG2, 1);
            }
            TC_COMMIT_MC2(mbF[buf]);   // arrives at BOTH CTAs' mbF[buf]
        }
    }

    // drain: last commit covers all previously issued MMAs
    {
        const int lastbuf = (nk - 1) & 1;
        MBAR_WAIT(mbF[lastbuf], phF[lastbuf]);
    }
    TC_FENCE_AFTER();

    if (HAS_BIAS) {
        ((float*)tilesg)[tid]       = bias[n0 + tid];
        ((float*)tilesg)[tid + 256] = bias[n0 + tid + 256];
        __syncthreads();
    }

    // epilogue: ALL 8 warps. Warps 0-3 (tid<128) do column chunks 0-1,
    // warps 4-7 (tid>=128) do chunks 2-3. Same TMEM lanes via tid&127.
    {
        const int half_id = tid >> 7;          // 0 or 1
        const int wg_tid  = tid & 127;
        const int row = m0 + wg_tid;
        const float* bsm = (const float*)tilesg;
        float rsum = 0.f;
        float rscale = 1.f;
        if (OUTM == 3) rscale = rinv[(long long)blockIdx.z * M + row];

        #pragma unroll
        for (int hh = 0; hh < 2; hh++) {
            const int h = half_id * 2 + hh;
            uint32_t d[128];
            TC_LD_X32(d +  0, tmem + h * 128 +  0);
            TC_LD_X32(d + 32, tmem + h * 128 + 32);
            TC_LD_X32(d + 64, tmem + h * 128 + 64);
            TC_LD_X32(d + 96, tmem + h * 128 + 96);
            TC_WAIT_LD();
            TC_FENCE_BEFORE();

            if (OUTM == 0) {
                float* cp = Cf + (long long)blockIdx.z * sC
                          + (long long)row * N + n0 + h * 128;
                #pragma unroll
                for (int c = 0; c < 128; c += 4) {
                    float4 o;
                    o.x = __uint_as_float(d[c + 0]);
                    o.y = __uint_as_float(d[c + 1]);
                    o.z = __uint_as_float(d[c + 2]);
                    o.w = __uint_as_float(d[c + 3]);
                    if (HAS_BIAS) {
                        o.x += bsm[h * 128 + c + 0]; o.y += bsm[h * 128 + c + 1];
                        o.z += bsm[h * 128 + c + 2]; o.w += bsm[h * 128 + c + 3];
                    }
                    *reinterpret_cast<float4*>(cp + c) = o;
                }
            } else {
                const long long rb = (long long)blockIdx.z * sC
                                   + (long long)row * N + n0 + h * 128;
                #pragma unroll
                for (int c = 0; c < 128; c += 8) {
                    float v[8];
                    #pragma unroll
                    for (int j = 0; j < 8; j++) {
                        v[j] = __uint_as_float(d[c + j]);
                        if (HAS_BIAS) v[j] += bsm[h * 128 + c + j];
                        if (OUTM == 2) { v[j] = __expf(escale * v[j]); rsum += v[j]; }
                        if (OUTM == 3) v[j] *= rscale;
                    }
                    uint4 hw, lw;
                    hw.x = pack_bf16(v[0], v[1]); hw.y = pack_bf16(v[2], v[3]);
                    hw.z = pack_bf16(v[4], v[5]); hw.w = pack_bf16(v[6], v[7]);
                    float l[8];
                    #pragma unroll
                    for (int j = 0; j < 8; j++) l[j] = v[j] - bf16_rn_f32(v[j]);
                    lw.x = pack_bf16(l[0], l[1]); lw.y = pack_bf16(l[2], l[3]);
                    lw.z = pack_bf16(l[4], l[5]); lw.w = pack_bf16(l[6], l[7]);
                    *reinterpret_cast<uint4*>(Chi + rb + c) = hw;
                    *reinterpret_cast<uint4*>(Clo + rb + c) = lw;
                }
            }
        }
        // two partial-sum slots per row per 512-tile (one per half_id)
        if (OUTM == 2)
            Prow[((long long)blockIdx.z * M + row) * (N >> 8)
                 + blockIdx.y * 2 + half_id] = rsum;
    }

    __syncthreads();
    if (tid == 0) {
        asm volatile("mbarrier.inval.shared.b64 [%0];" :: "r"(mbF[0]) : "memory");
        asm volatile("mbarrier.inval.shared.b64 [%0];" :: "r"(mbF[1]) : "memory");
        asm volatile("mbarrier.inval.shared.b64 [%0];" :: "r"(mbR[0]) : "memory");
        asm volatile("mbarrier.inval.shared.b64 [%0];" :: "r"(mbR[1]) : "memory");
    }
    __syncthreads();
    if (tid < 32) { TC_RELINQ_CG2(); TC_DEALLOC_CG2(tmem, 512); }
    CLUSTER_SYNC();

#else
    // ================= SIMT fallback (base target; never selected) =========
    float (*As)[128] = reinterpret_cast<float (*)[128]>(smem);
    float (*Bs)[128] = reinterpret_cast<float (*)[128]>(smem + 4096);

    const int ty = tid >> 4, tx = tid & 15;
    const int aRow = tid >> 1, aCol = (tid & 1) * 4;

    for (int half = 0; half < 4; half++) {
        const int n0h = n0 + half * 128;
        float acc[8][8] = {};
        for (int k0 = 0; k0 < K; k0 += 8) {
            #pragma unroll
            for (int e = 0; e < 4; e++) {
                long long ia = (long long)(m0 + aRow) * K + k0 + aCol + e;
                As[aCol + e][aRow] = __bfloat162float(Ahi[ia]) + __bfloat162float(Alo[ia]);
                long long ib = (long long)(n0h + aRow) * K + k0 + aCol + e;
                Bs[aCol + e][aRow] = __bfloat162float(Bhi[ib]) + __bfloat162float(Blo[ib]);
            }
            __syncthreads();
            #pragma unroll
            for (int kk = 0; kk < 8; kk++) {
                float ra[8], rb[8];
                #pragma unroll
                for (int i = 0; i < 8; i++) ra[i] = As[kk][ty * 8 + i];
                #pragma unroll
                for (int j = 0; j < 8; j++) rb[j] = Bs[kk][tx * 8 + j];
                #pragma unroll
                for (int i = 0; i < 8; i++)
                    #pragma unroll
                    for (int j = 0; j < 8; j++)
                        acc[i][j] = fmaf(ra[i], rb[j], acc[i][j]);
            }
            __syncthreads();
        }
        #pragma unroll
        for (int i = 0; i < 8; i++) {
            const int row = m0 + ty * 8 + i;
            float psum = 0.f;
            #pragma unroll
            for (int j = 0; j < 8; j++) {
                const int col = n0h + tx * 8 + j;
                float val = acc[i][j] + (HAS_BIAS ? bias[col] : 0.f);
                if (OUTM == 2) { val = __expf(escale * val); psum += val; }
                if (OUTM == 3) val *= rinv[(long long)blockIdx.z * M + row];
                long long o = (long long)blockIdx.z * sC + (long long)row * N + col;
                if (OUTM == 0) {
                    Cf[o] = val;
                } else {
                    float hh = bf16_rn_f32(val);
                    Chi[o] = __float2bfloat16(val);
                    Clo[o] = __float2bfloat16(val - hh);
                }
            }
            if (OUTM == 2)
                atomicAdd(&Prow[((long long)blockIdx.z * M + row) * (N >> 8)
                                + blockIdx.y * 2 + (half >> 1)], psum);
        }
        __syncthreads();
    }
#endif
}

// ---------------------------------------------------------------------------
// rowinv: rinv[i] = 1 / sum_t P[i][t]
// ---------------------------------------------------------------------------
__global__ __launch_bounds__(256)
void rowinv_k(const float* __restrict__ P, float* __restrict__ rinv, int ntile)
{
    int i = blockIdx.x * blockDim.x + threadIdx.x;
    if (i >= NB * NSEQ) return;
    const float* p = P + (long long)i * ntile;
    float s = 0.f;
    for (int t = 0; t < ntile; t++) s += p[t];
    rinv[i] = 1.0f / s;
}

// ---------------------------------------------------------------------------
// Elementwise fp32 -> bf16 hi/lo split (n4 = count of float4 groups)
// ---------------------------------------------------------------------------
__global__ __launch_bounds__(256)
void conv_k(const float* __restrict__ in, bf16* __restrict__ oh,
            bf16* __restrict__ ol, long long n4)
{
    long long idx = (long long)blockIdx.x * blockDim.x + threadIdx.x;
    if (idx >= n4) return;
    float4 v = reinterpret_cast<const float4*>(in)[idx];
    uint2 hw, lw;
    hw.x = pack_bf16(v.x, v.y); hw.y = pack_bf16(v.z, v.w);
    lw.x = pack_bf16(v.x - bf16_rn_f32(v.x), v.y - bf16_rn_f32(v.y));
    lw.y = pack_bf16(v.z - bf16_rn_f32(v.z), v.w - bf16_rn_f32(v.w));
    reinterpret_cast<uint2*>(oh)[idx] = hw;
    reinterpret_cast<uint2*>(ol)[idx] = lw;
}

// ---------------------------------------------------------------------------
// 32x32 tiled transpose fp32 -> bf16 hi/lo
// ---------------------------------------------------------------------------
__global__ __launch_bounds__(256)
void transpose_conv_k(const float* __restrict__ in,
                      bf16* __restrict__ oh, bf16* __restrict__ ol,
                      int R, int Cc, long long sIn, long long sOut)
{
    __shared__ float t[32][33];
    in += (long long)blockIdx.z * sIn;
    const long long ob = (long long)blockIdx.z * sOut;
    const int r0 = blockIdx.y * 32, c0 = blockIdx.x * 32;
    const int tx = threadIdx.x & 31, ty = threadIdx.x >> 5;
    #pragma unroll
    for (int i = 0; i < 32; i += 8)
        t[ty + i][tx] = in[(long long)(r0 + ty + i) * Cc + c0 + tx];
    __syncthreads();
    #pragma unroll
    for (int i = 0; i < 32; i += 8) {
        float v = t[tx][ty + i];
        float h = bf16_rn_f32(v);
        long long o = ob + (long long)(c0 + ty + i) * R + r0 + tx;
        oh[o] = __float2bfloat16(v);
        ol[o] = __float2bfloat16(v - h);
    }
}

// ---------------------------------------------------------------------------
extern "C" void kernel_launch(void* const* d_in, const int* in_sizes, int n_in,
                              void* d_out, int out_size)
{
    const float* x  = (const float*)d_in[0];
    const float* Wq = (const float*)d_in[1];
    const float* bq = (const float*)d_in[2];
    const float* Wk = (const float*)d_in[3];
    const float* bk = (const float*)d_in[4];
    const float* Wv = (const float*)d_in[5];
    const float* bv = (const float*)d_in[6];
    const float* Wo = (const float*)d_in[7];
    const float* bo = (const float*)d_in[8];
    float* out = (float*)d_out;

    const int M = NB * NSEQ;
    const float scale = 0.03125f;

    bf16 *xh, *xl, *wth, *wtl, *qh, *ql, *kh, *kl, *vth, *vtl, *ah, *al, *aoh, *aol;
    float *v, *P, *rinv;
    cudaGetSymbolAddress((void**)&xh,  g_xh);  cudaGetSymbolAddress((void**)&xl,  g_xl);
    cudaGetSymbolAddress((void**)&wth, g_wth); cudaGetSymbolAddress((void**)&wtl, g_wtl);
    cudaGetSymbolAddress((void**)&qh,  g_qh);  cudaGetSymbolAddress((void**)&ql,  g_ql);
    cudaGetSymbolAddress((void**)&kh,  g_kh);  cudaGetSymbolAddress((void**)&kl,  g_kl);
    cudaGetSymbolAddress((void**)&v,   g_v);
    cudaGetSymbolAddress((void**)&vth, g_vth); cudaGetSymbolAddress((void**)&vtl, g_vtl);
    cudaGetSymbolAddress((void**)&ah,  g_ah);  cudaGetSymbolAddress((void**)&al,  g_al);
    cudaGetSymbolAddress((void**)&aoh, g_aoh); cudaGetSymbolAddress((void**)&aol, g_aol);
    cudaGetSymbolAddress((void**)&P,   g_P);   cudaGetSymbolAddress((void**)&rinv, g_rinv);

    cudaFuncSetAttribute((const void*)tc_gemm6<0, true>,  cudaFuncAttributeMaxDynamicSharedMemorySize, SMEM_BYTES);
    cudaFuncSetAttribute((const void*)tc_gemm6<1, true>,  cudaFuncAttributeMaxDynamicSharedMemorySize, SMEM_BYTES);
    cudaFuncSetAttribute((const void*)tc_gemm6<2, false>, cudaFuncAttributeMaxDynamicSharedMemorySize, SMEM_BYTES);
    cudaFuncSetAttribute((const void*)tc_gemm6<3, false>, cudaFuncAttributeMaxDynamicSharedMemorySize, SMEM_BYTES);

    const long long qkv = (long long)NSEQ * DIMC;
    const long long ss  = (long long)NSEQ * NSEQ;

    dim3 b256(256);

    // 1) split x -> xh/xl
    conv_k<<<16384, b256>>>(x, xh, xl, 4194304);

    // 2) transpose+split weights
    {
        dim3 g(32, 32, 1);
        transpose_conv_k<<<g, b256>>>(Wq, wth + 0*1048576, wtl + 0*1048576, DIMC, DIMC, 0, 0);
        transpose_conv_k<<<g, b256>>>(Wk, wth + 1*1048576, wtl + 1*1048576, DIMC, DIMC, 0, 0);
        transpose_conv_k<<<g, b256>>>(Wv, wth + 2*1048576, wtl + 2*1048576, DIMC, DIMC, 0, 0);
        transpose_conv_k<<<g, b256>>>(Wo, wth + 3*1048576, wtl + 3*1048576, DIMC, DIMC, 0, 0);
    }

    // 3) q,k (bf16 pair out) and v (fp32 out) projections
    {
        dim3 g(M / 128, DIMC / BNC, 1);
        tc_gemm6<1, true><<<g, b256, SMEM_BYTES>>>(xh, xl, wth + 0*1048576, wtl + 0*1048576,
                                                   bq, nullptr, qh, ql, nullptr, nullptr, 0.f,
                                                   M, DIMC, DIMC, 0, 0, 0);
        tc_gemm6<1, true><<<g, b256, SMEM_BYTES>>>(xh, xl, wth + 1*1048576, wtl + 1*1048576,
                                                   bk, nullptr, kh, kl, nullptr, nullptr, 0.f,
                                                   M, DIMC, DIMC, 0, 0, 0);
        tc_gemm6<0, true><<<g, b256, SMEM_BYTES>>>(xh, xl, wth + 2*1048576, wtl + 2*1048576,
                                                   bv, v, nullptr, nullptr, nullptr, nullptr, 0.f,
                                                   M, DIMC, DIMC, 0, 0, 0);
    }

    // 4) vT split per batch
    {
        dim3 g(DIMC / 32, NSEQ / 32, NB);
        transpose_conv_k<<<g, b256>>>(v, vth, vtl, NSEQ, DIMC, qkv, qkv);
    }

    // 5) e = exp(scale * q@k^T)  -> ah/al (unnormalized) + row partials
    {
        dim3 g(NSEQ / 128, NSEQ / BNC, NB);
        tc_gemm6<2, false><<<g, b256, SMEM_BYTES>>>(qh, ql, kh, kl, nullptr,
                                                    nullptr, ah, al, nullptr, P, scale,
                                                    NSEQ, NSEQ, DIMC, qkv, qkv, ss);
    }

    // 6) rinv = 1/rowsum  (ntile = 2 slots per 512-wide tile)
    rowinv_k<<<64, b256>>>(P, rinv, NSEQ >> 8);

    // 7) ao = (e @ vT^T) * rinv  (bf16 pair out), K = 4096
    {
        dim3 g(NSEQ / 128, DIMC / BNC, NB);
        tc_gemm6<3, false><<<g, b256, SMEM_BYTES>>>(ah, al, vth, vtl, nullptr,
                                                    nullptr, aoh, aol, rinv, nullptr, 0.f,
                                                    NSEQ, DIMC, NSEQ, ss, qkv, qkv);
    }

    // 8) out = ao @ WoT^T + bo (fp32 out)
    {
        dim3 g(M / 128, DIMC / BNC, 1);
        tc_gemm6<0, true><<<g, b256, SMEM_BYTES>>>(aoh, aol, wth + 3*1048576, wtl + 3*1048576,
                                                   bo, out, nullptr, nullptr, nullptr, nullptr, 0.f,
                                                   M, DIMC, DIMC, 0, 0, 0);
    }
}

// round 16
// speedup vs baseline: 1.3517x; 1.3517x over previous
#include <cuda_runtime.h>
#include <cuda_bf16.h>
#include <cstdint>

// ---------------------------------------------------------------------------
// NaiveAttention on GB300. B=4, N=4096, C=1024 fp32.
// R16: R14 + MMA(t) enqueued BEFORE waiting on MMA(t-1) completion.
// The tcgen05 queue never drains at tile boundaries; the mbF wait now gates
// only the cp.async refill of the freed buffer.
// ---------------------------------------------------------------------------

#if !defined(__CUDA_ARCH__)
#define USE_TC 1
#elif defined(__CUDA_ARCH_FEAT_SM103_ALL) || defined(__CUDA_ARCH_FEAT_SM100_ALL) || \
      defined(__CUDA_ARCH_FEAT_SM101_ALL) || defined(__CUDA_ARCH_SPECIFIC__) || \
      defined(__CUDA_ARCH_FAMILY_SPECIFIC__)
#define USE_TC 1
#else
#define USE_TC 0
#endif

#define DIMC 1024
#define NSEQ 4096
#define NB   4

typedef __nv_bfloat16 bf16;

// Scratch (device globals — no allocation allowed).
__device__ bf16  g_xh [16777216], g_xl [16777216];
__device__ bf16  g_wth[4194304],  g_wtl[4194304];
__device__ bf16  g_qh [16777216], g_ql [16777216];
__device__ bf16  g_kh [16777216], g_kl [16777216];
__device__ float g_v  [16777216];
__device__ bf16  g_vth[16777216], g_vtl[16777216];
__device__ bf16  g_ah [67108864], g_al [67108864];   // exp(scores) hi/lo (unnormalized)
__device__ bf16  g_aoh[16777216], g_aol[16777216];
__device__ float g_P  [262144];                       // row partial sums
__device__ float g_rinv[16384];                       // 1/rowsum

#define KT 64
#define BNC 512      // cluster N tile (two 256 halves)
// idesc kind::f16 cg2: dtype=F32(1<<4), a=b=BF16(1<<7|1<<10), N=256(32<<17), M=256(16<<24)
#define IDESC_CG2 0x10400490u
// Stage per CTA: Ahi16K@0 Alo@16K | B0hi@32K B0lo@48K | B1hi@64K B1lo@80K
#define BUF_BYTES 98304
#define NSTAGE 2
#define SMEM_BYTES (2048 + NSTAGE * BUF_BYTES)

// ---- bf16 helpers (legal on base target too) ------------------------------
__device__ __forceinline__ uint32_t pack_bf16(float lo, float hi) {
    uint32_t r;
    asm("cvt.rn.satfinite.bf16x2.f32 %0, %1, %2;" : "=r"(r) : "f"(hi), "f"(lo));
    return r;
}
__device__ __forceinline__ float bf16_rn_f32(float x) {
    uint32_t r;
    asm("cvt.rn.satfinite.bf16x2.f32 %0, %1, %1;" : "=r"(r) : "f"(x));
    return __uint_as_float(r << 16);
}

#if USE_TC
// ---------------------------------------------------------------------------
// sm_103a-only PTX helpers
// ---------------------------------------------------------------------------
__device__ __forceinline__ uint32_t smem_u32(const void* p) {
    uint32_t a;
    asm("{ .reg .u64 t; cvta.to.shared.u64 t, %1; cvt.u32.u64 %0, t; }"
        : "=r"(a) : "l"(p));
    return a;
}

#define MBAR_INIT(addr, cnt) \
    asm volatile("mbarrier.init.shared.b64 [%0], %1;" :: "r"(addr), "r"(cnt) : "memory")

// local wait, cta-scope acquire
#define MBAR_WAIT(addr, ph) do {                                              \
    uint32_t _m = (addr); uint32_t _p = (ph); uint32_t _done;                 \
    asm volatile("{\n\t.reg .pred p;\n\t"                                     \
        "mbarrier.try_wait.parity.acquire.cta.shared::cta.b64 p, [%1], %2;\n\t" \
        "selp.b32 %0, 1, 0, p;\n\t}"                                          \
        : "=r"(_done) : "r"(_m), "r"(_p) : "memory");                         \
    if (!_done) {                                                             \
        asm volatile("{\n\t.reg .pred P1;\n\t"                                \
            "WL_%=:\n\t"                                                      \
            "mbarrier.try_wait.parity.acquire.cta.shared::cta.b64 P1, [%0], %1, 0x989680;\n\t" \
            "@P1 bra.uni WD_%=;\n\t"                                          \
            "bra.uni WL_%=;\n\t"                                              \
            "WD_%=:\n\t}"                                                     \
            :: "r"(_m), "r"(_p) : "memory");                                  \
    }                                                                         \
} while (0)

// local wait, cluster-scope acquire (protects peer-CTA SMEM reads by cg2 MMA)
#define MBAR_WAIT_CL(addr, ph) do {                                           \
    uint32_t _m = (addr); uint32_t _p = (ph); uint32_t _done;                 \
    asm volatile("{\n\t.reg .pred p;\n\t"                                     \
        "mbarrier.try_wait.parity.acquire.cluster.shared::cta.b64 p, [%1], %2;\n\t" \
        "selp.b32 %0, 1, 0, p;\n\t}"                                          \
        : "=r"(_done) : "r"(_m), "r"(_p) : "memory");                         \
    if (!_done) {                                                             \
        asm volatile("{\n\t.reg .pred P1;\n\t"                                \
            "WL_%=:\n\t"                                                      \
            "mbarrier.try_wait.parity.acquire.cluster.shared::cta.b64 P1, [%0], %1, 0x989680;\n\t" \
            "@P1 bra.uni WD_%=;\n\t"                                          \
            "bra.uni WL_%=;\n\t"                                              \
            "WD_%=:\n\t}"                                                     \
            :: "r"(_m), "r"(_p) : "memory");                                  \
    }                                                                         \
} while (0)

// arrive on cluster-rank-0's mbarrier at the same SMEM offset (mapa)
#define MBAR_ARRIVE_R0(addr) \
    asm volatile("{\n\t.reg .b32 ra;\n\t" \
        "mapa.shared::cluster.u32 ra, %0, %1;\n\t" \
        "mbarrier.arrive.shared::cluster.b64 _, [ra];\n\t}" \
        :: "r"(addr), "r"(0) : "memory")

#define CLUSTER_SYNC() do { \
    asm volatile("barrier.cluster.arrive.aligned;" ::: "memory"); \
    asm volatile("barrier.cluster.wait.aligned;" ::: "memory"); \
} while (0)

#define TC_ALLOC_CG2(sm, n)  asm volatile("tcgen05.alloc.cta_group::2.sync.aligned.shared::cta.b32 [%0], %1;" :: "r"(sm), "r"(n) : "memory")
#define TC_DEALLOC_CG2(t, n) asm volatile("tcgen05.dealloc.cta_group::2.sync.aligned.b32 %0, %1;" :: "r"(t), "r"(n))
#define TC_RELINQ_CG2()      asm volatile("tcgen05.relinquish_alloc_permit.cta_group::2.sync.aligned;")
#define TC_COMMIT_MC2(mb)    asm volatile("tcgen05.commit.cta_group::2.mbarrier::arrive::one.shared::cluster.multicast::cluster.b64 [%0], %1;" :: "r"(mb), "h"((uint16_t)0x3) : "memory")
#define TC_FENCE_AFTER()  asm volatile("tcgen05.fence::after_thread_sync;" ::: "memory")
#define TC_FENCE_BEFORE() asm volatile("tcgen05.fence::before_thread_sync;" ::: "memory")
#define TC_WAIT_LD()      asm volatile("tcgen05.wait::ld.sync.aligned;" ::: "memory")
#define FENCE_ASYNC()     asm volatile("fence.proxy.async.shared::cta;" ::: "memory")

#define CP_ASYNC16(sm, gp) \
    asm volatile("cp.async.cg.shared.global [%0], [%1], 16;" :: "r"(sm), "l"(gp) : "memory")
#define CP_COMMIT() asm volatile("cp.async.commit_group;" ::: "memory")
#define CP_WAIT0()  asm volatile("cp.async.wait_group 0;" ::: "memory")

#define TC_LD_X32(r, a) \
    asm volatile("tcgen05.ld.sync.aligned.32x32b.x32.b32 " \
        "{%0, %1, %2, %3, %4, %5, %6, %7, %8, %9, %10, %11, %12, %13, %14, %15, " \
        " %16, %17, %18, %19, %20, %21, %22, %23, %24, %25, %26, %27, %28, %29, %30, %31}, [%32];" \
        : "=r"((r)[0]), "=r"((r)[1]), "=r"((r)[2]), "=r"((r)[3]), \
          "=r"((r)[4]), "=r"((r)[5]), "=r"((r)[6]), "=r"((r)[7]), \
          "=r"((r)[8]), "=r"((r)[9]), "=r"((r)[10]), "=r"((r)[11]), \
          "=r"((r)[12]), "=r"((r)[13]), "=r"((r)[14]), "=r"((r)[15]), \
          "=r"((r)[16]), "=r"((r)[17]), "=r"((r)[18]), "=r"((r)[19]), \
          "=r"((r)[20]), "=r"((r)[21]), "=r"((r)[22]), "=r"((r)[23]), \
          "=r"((r)[24]), "=r"((r)[25]), "=r"((r)[26]), "=r"((r)[27]), \
          "=r"((r)[28]), "=r"((r)[29]), "=r"((r)[30]), "=r"((r)[31]) \
        : "r"(a))

// cg2 bf16 SS MMA (8-register disable-output-lane vector)
__device__ __forceinline__ void mma_f16_ss_cg2(uint32_t d, uint64_t a, uint64_t b,
                                               uint32_t idesc, uint32_t en) {
    asm volatile("{\n\t.reg .pred p;\n\tsetp.ne.u32 p, %4, 0;\n\t"
        "tcgen05.mma.cta_group::2.kind::f16 [%0], %1, %2, %3, "
        "{%5, %5, %5, %5, %5, %5, %5, %5}, p;\n\t}"
        :: "r"(d), "l"(a), "l"(b), "r"(idesc), "r"(en), "r"(0u) : "memory");
}

__device__ __forceinline__ uint64_t mk_desc(uint32_t addr) {
    const uint64_t base = (uint64_t(2) << 61) | (uint64_t(1) << 46)
                        | (uint64_t(64) << 32) | (uint64_t(1) << 16);
    return base | ((uint64_t)(addr >> 4) & 0x3FFF);
}

__device__ __forceinline__ uint32_t sw128(uint32_t off) {
    return off ^ ((off >> 3) & 0x70);
}
#endif  // USE_TC

// ---------------------------------------------------------------------------
// GEMM (2-CTA clusters, 256M x 512N per cluster):
//   C[z] = (Ahi+Alo)[z] @ (Bhi+Blo)[z]^T.
//   OUTM=0: Cf fp32 (+bias).  OUTM=1: Chi/Clo bf16 pair (+bias).
//   OUTM=2: e=exp(escale*acc) -> pair + row partials.  OUTM=3: acc*rinv[row].
//   Grid: x = M/128 (cluster dim 2 on x), y = N/512, z = batch.
//   M % 256 == 0, N % 512 == 0, K % 64 == 0.
// ---------------------------------------------------------------------------
template <int OUTM, bool HAS_BIAS>
__global__ __launch_bounds__(256, 1) __cluster_dims__(2, 1, 1)
void tc_gemm7(const bf16* __restrict__ Ahi, const bf16* __restrict__ Alo,
              const bf16* __restrict__ Bhi, const bf16* __restrict__ Blo,
              const float* __restrict__ bias,
              float* __restrict__ Cf, bf16* __restrict__ Chi, bf16* __restrict__ Clo,
              const float* __restrict__ rinv, float* __restrict__ Prow, float escale,
              int M, int N, int K,
              long long sA, long long sB, long long sC)
{
    extern __shared__ char smem[];

    Ahi += (long long)blockIdx.z * sA;  Alo += (long long)blockIdx.z * sA;
    Bhi += (long long)blockIdx.z * sB;  Blo += (long long)blockIdx.z * sB;

    const int tid  = threadIdx.x;
    const int rank = blockIdx.x & 1;                  // == cluster_ctarank
    const int m0   = blockIdx.x * 128;                // includes rank offset
    const int n0   = blockIdx.y * BNC;                // 512-wide N tile

#if USE_TC
    const uint32_t sb    = smem_u32(smem);
    const uint32_t tiles = (sb + 64 + 1023) & ~1023u;
    char* tilesg = smem + (tiles - sb);
    const uint32_t mbF[NSTAGE] = { sb,      sb + 8  };   // MMA-done (both CTAs)
    const uint32_t mbR[NSTAGE] = { sb + 16, sb + 24 };   // loads-ready (rank0)
    const uint32_t tptr = sb + 32;

    if (tid < 32) TC_ALLOC_CG2(tptr, 512);
    if (tid == 0) {
        MBAR_INIT(mbF[0], 1); MBAR_INIT(mbF[1], 1);
        MBAR_INIT(mbR[0], 2); MBAR_INIT(mbR[1], 2);
    }
    __syncthreads();
    uint32_t tmem;
    asm volatile("ld.shared.b32 %0, [%1];" : "=r"(tmem) : "r"(tptr));

    // All mbarriers + TMEM alloc visible cluster-wide before any traffic.
    CLUSTER_SYNC();

    const int nk = K / KT;
    int phF[NSTAGE] = { 0, 0 };
    int phR = 0, stR = 0;

    // loader geometry: 2 threads per row, 64B half-rows.
    const int lrow  = tid >> 1;          // 0..127
    const int lhalf = tid & 1;
    const long long aoff  = (long long)(m0 + lrow) * K + lhalf * 32;
    const long long boff0 = (long long)(n0 +       rank * 128 + lrow) * K + lhalf * 32;
    const long long boff1 = (long long)(n0 + 256 + rank * 128 + lrow) * K + lhalf * 32;
    const uint32_t soff   = (uint32_t)(lrow * 128 + lhalf * 64);

    auto load_tile = [&](int tt, uint32_t sbase) {
        const long long kof = (long long)tt * KT;
        const bf16* p0 = Ahi + aoff  + kof;
        const bf16* p1 = Alo + aoff  + kof;
        const bf16* p2 = Bhi + boff0 + kof;
        const bf16* p3 = Blo + boff0 + kof;
        const bf16* p4 = Bhi + boff1 + kof;
        const bf16* p5 = Blo + boff1 + kof;
        #pragma unroll
        for (int j = 0; j < 4; j++) CP_ASYNC16(sbase +         sw128(soff + j * 16), p0 + j * 8);
        #pragma unroll
        for (int j = 0; j < 4; j++) CP_ASYNC16(sbase + 16384 + sw128(soff + j * 16), p1 + j * 8);
        #pragma unroll
        for (int j = 0; j < 4; j++) CP_ASYNC16(sbase + 32768 + sw128(soff + j * 16), p2 + j * 8);
        #pragma unroll
        for (int j = 0; j < 4; j++) CP_ASYNC16(sbase + 49152 + sw128(soff + j * 16), p3 + j * 8);
        #pragma unroll
        for (int j = 0; j < 4; j++) CP_ASYNC16(sbase + 65536 + sw128(soff + j * 16), p4 + j * 8);
        #pragma unroll
        for (int j = 0; j < 4; j++) CP_ASYNC16(sbase + 81920 + sw128(soff + j * 16), p5 + j * 8);
    };

    // prologue: tile 0 -> buf 0
    load_tile(0, tiles);
    CP_COMMIT();

    for (int t = 0; t < nk; t++) {
        const int buf = t & 1;
        const uint32_t sbase = tiles + buf * BUF_BYTES;

        // ---- loads(t) complete -> signal ready -> ENQUEUE MMA(t) ----
        CP_WAIT0();               // loads for tile t are done (only group left)
        FENCE_ASYNC();
        __syncthreads();
        if (tid == 0) MBAR_ARRIVE_R0(mbR[buf]);

        if (rank == 0 && tid == 0) {
            MBAR_WAIT_CL(mbR[stR], phR);
            if (++stR == NSTAGE) { stR = 0; phR ^= 1; }
            uint64_t ah = mk_desc(sbase);
            uint64_t al = mk_desc(sbase + 16384);
            #pragma unroll
            for (int h = 0; h < 2; h++) {
                uint64_t bh = mk_desc(sbase + 32768 + h * 32768);
                uint64_t bl = mk_desc(sbase + 49152 + h * 32768);
                const uint32_t dt = tmem + h * 256;
                #pragma unroll
                for (int kc = 0; kc < 4; kc++)
                    mma_f16_ss_cg2(dt, ah + kc * 2, bh + kc * 2, IDESC_CG2, (t | kc) != 0);
                #pragma unroll
                for (int kc = 0; kc < 4; kc++)
                    mma_f16_ss_cg2(dt, ah + kc * 2, bl + kc * 2, IDESC_CG2, 1);
                #pragma unroll
                for (int kc = 0; kc < 4; kc++)
                    mma_f16_ss_cg2(dt, al + kc * 2, bh + kc * 2, IDESC_CG2, 1);
            }
            TC_COMMIT_MC2(mbF[buf]);   // arrives at BOTH CTAs' mbF[buf]
        }

        // ---- AFTER MMA(t) is queued: free + refill the other buffer ----
        const int tp = t + 1;
        if (tp < nk) {
            const int nbuf = tp & 1;
            if (tp >= NSTAGE) { MBAR_WAIT(mbF[nbuf], phF[nbuf]); phF[nbuf] ^= 1; }
            load_tile(tp, tiles + nbuf * BUF_BYTES);
            CP_COMMIT();
        }
    }

    // drain: last commit covers all previously issued MMAs
    {
        const int lastbuf = (nk - 1) & 1;
        MBAR_WAIT(mbF[lastbuf], phF[lastbuf]);
    }
    TC_FENCE_AFTER();

    if (HAS_BIAS) {
        ((float*)tilesg)[tid]       = bias[n0 + tid];
        ((float*)tilesg)[tid + 256] = bias[n0 + tid + 256];
        __syncthreads();
    }

    // epilogue: each CTA reads its 128 TMEM lanes x 512 cols (4 chunks)
    if (tid < 128) {
        const int row = m0 + tid;
        const float* bsm = (const float*)tilesg;
        float rsum = 0.f;
        float rscale = 1.f;
        if (OUTM == 3) rscale = rinv[(long long)blockIdx.z * M + row];

        #pragma unroll
        for (int h = 0; h < 4; h++) {
            uint32_t d[128];
            TC_LD_X32(d +  0, tmem + h * 128 +  0);
            TC_LD_X32(d + 32, tmem + h * 128 + 32);
            TC_LD_X32(d + 64, tmem + h * 128 + 64);
            TC_LD_X32(d + 96, tmem + h * 128 + 96);
            TC_WAIT_LD();
            TC_FENCE_BEFORE();

            if (OUTM == 0) {
                float* cp = Cf + (long long)blockIdx.z * sC
                          + (long long)row * N + n0 + h * 128;
                #pragma unroll
                for (int c = 0; c < 128; c += 4) {
                    float4 o;
                    o.x = __uint_as_float(d[c + 0]);
                    o.y = __uint_as_float(d[c + 1]);
                    o.z = __uint_as_float(d[c + 2]);
                    o.w = __uint_as_float(d[c + 3]);
                    if (HAS_BIAS) {
                        o.x += bsm[h * 128 + c + 0]; o.y += bsm[h * 128 + c + 1];
                        o.z += bsm[h * 128 + c + 2]; o.w += bsm[h * 128 + c + 3];
                    }
                    *reinterpret_cast<float4*>(cp + c) = o;
                }
            } else {
                const long long rb = (long long)blockIdx.z * sC
                                   + (long long)row * N + n0 + h * 128;
                #pragma unroll
                for (int c = 0; c < 128; c += 8) {
                    float v[8];
                    #pragma unroll
                    for (int j = 0; j < 8; j++) {
                        v[j] = __uint_as_float(d[c + j]);
                        if (HAS_BIAS) v[j] += bsm[h * 128 + c + j];
                        if (OUTM == 2) { v[j] = __expf(escale * v[j]); rsum += v[j]; }
                        if (OUTM == 3) v[j] *= rscale;
                    }
                    uint4 hw, lw;
                    hw.x = pack_bf16(v[0], v[1]); hw.y = pack_bf16(v[2], v[3]);
                    hw.z = pack_bf16(v[4], v[5]); hw.w = pack_bf16(v[6], v[7]);
                    float l[8];
                    #pragma unroll
                    for (int j = 0; j < 8; j++) l[j] = v[j] - bf16_rn_f32(v[j]);
                    lw.x = pack_bf16(l[0], l[1]); lw.y = pack_bf16(l[2], l[3]);
                    lw.z = pack_bf16(l[4], l[5]); lw.w = pack_bf16(l[6], l[7]);
                    *reinterpret_cast<uint4*>(Chi + rb + c) = hw;
                    *reinterpret_cast<uint4*>(Clo + rb + c) = lw;
                }
            }
        }
        if (OUTM == 2)
            Prow[((long long)blockIdx.z * M + row) * (N >> 9) + blockIdx.y] = rsum;
    }

    __syncthreads();
    if (tid == 0) {
        asm volatile("mbarrier.inval.shared.b64 [%0];" :: "r"(mbF[0]) : "memory");
        asm volatile("mbarrier.inval.shared.b64 [%0];" :: "r"(mbF[1]) : "memory");
        asm volatile("mbarrier.inval.shared.b64 [%0];" :: "r"(mbR[0]) : "memory");
        asm volatile("mbarrier.inval.shared.b64 [%0];" :: "r"(mbR[1]) : "memory");
    }
    __syncthreads();
    if (tid < 32) { TC_RELINQ_CG2(); TC_DEALLOC_CG2(tmem, 512); }
    CLUSTER_SYNC();

#else
    // ================= SIMT fallback (base target; never selected) =========
    float (*As)[128] = reinterpret_cast<float (*)[128]>(smem);
    float (*Bs)[128] = reinterpret_cast<float (*)[128]>(smem + 4096);

    const int ty = tid >> 4, tx = tid & 15;
    const int aRow = tid >> 1, aCol = (tid & 1) * 4;

    for (int half = 0; half < 4; half++) {
        const int n0h = n0 + half * 128;
        float acc[8][8] = {};
        for (int k0 = 0; k0 < K; k0 += 8) {
            #pragma unroll
            for (int e = 0; e < 4; e++) {
                long long ia = (long long)(m0 + aRow) * K + k0 + aCol + e;
                As[aCol + e][aRow] = __bfloat162float(Ahi[ia]) + __bfloat162float(Alo[ia]);
                long long ib = (long long)(n0h + aRow) * K + k0 + aCol + e;
                Bs[aCol + e][aRow] = __bfloat162float(Bhi[ib]) + __bfloat162float(Blo[ib]);
            }
            __syncthreads();
            #pragma unroll
            for (int kk = 0; kk < 8; kk++) {
                float ra[8], rb[8];
                #pragma unroll
                for (int i = 0; i < 8; i++) ra[i] = As[kk][ty * 8 + i];
                #pragma unroll
                for (int j = 0; j < 8; j++) rb[j] = Bs[kk][tx * 8 + j];
                #pragma unroll
                for (int i = 0; i < 8; i++)
                    #pragma unroll
                    for (int j = 0; j < 8; j++)
                        acc[i][j] = fmaf(ra[i], rb[j], acc[i][j]);
            }
            __syncthreads();
        }
        #pragma unroll
        for (int i = 0; i < 8; i++) {
            const int row = m0 + ty * 8 + i;
            float psum = 0.f;
            #pragma unroll
            for (int j = 0; j < 8; j++) {
                const int col = n0h + tx * 8 + j;
                float val = acc[i][j] + (HAS_BIAS ? bias[col] : 0.f);
                if (OUTM == 2) { val = __expf(escale * val); psum += val; }
                if (OUTM == 3) val *= rinv[(long long)blockIdx.z * M + row];
                long long o = (long long)blockIdx.z * sC + (long long)row * N + col;
                if (OUTM == 0) {
                    Cf[o] = val;
                } else {
                    float hh = bf16_rn_f32(val);
                    Chi[o] = __float2bfloat16(val);
                    Clo[o] = __float2bfloat16(val - hh);
                }
            }
            if (OUTM == 2)
                atomicAdd(&Prow[((long long)blockIdx.z * M + row) * (N >> 9) + blockIdx.y], psum);
        }
        __syncthreads();
    }
#endif
}

// ---------------------------------------------------------------------------
// rowinv: rinv[i] = 1 / sum_t P[i][t]
// ---------------------------------------------------------------------------
__global__ __launch_bounds__(256)
void rowinv_k(const float* __restrict__ P, float* __restrict__ rinv, int ntile)
{
    int i = blockIdx.x * blockDim.x + threadIdx.x;
    if (i >= NB * NSEQ) return;
    const float* p = P + (long long)i * ntile;
    float s = 0.f;
    for (int t = 0; t < ntile; t++) s += p[t];
    rinv[i] = 1.0f / s;
}

// ---------------------------------------------------------------------------
// Elementwise fp32 -> bf16 hi/lo split (n4 = count of float4 groups)
// ---------------------------------------------------------------------------
__global__ __launch_bounds__(256)
void conv_k(const float* __restrict__ in, bf16* __restrict__ oh,
            bf16* __restrict__ ol, long long n4)
{
    long long idx = (long long)blockIdx.x * blockDim.x + threadIdx.x;
    if (idx >= n4) return;
    float4 v = reinterpret_cast<const float4*>(in)[idx];
    uint2 hw, lw;
    hw.x = pack_bf16(v.x, v.y); hw.y = pack_bf16(v.z, v.w);
    lw.x = pack_bf16(v.x - bf16_rn_f32(v.x), v.y - bf16_rn_f32(v.y));
    lw.y = pack_bf16(v.z - bf16_rn_f32(v.z), v.w - bf16_rn_f32(v.w));
    reinterpret_cast<uint2*>(oh)[idx] = hw;
    reinterpret_cast<uint2*>(ol)[idx] = lw;
}

// ---------------------------------------------------------------------------
// 32x32 tiled transpose fp32 -> bf16 hi/lo
// ---------------------------------------------------------------------------
__global__ __launch_bounds__(256)
void transpose_conv_k(const float* __restrict__ in,
                      bf16* __restrict__ oh, bf16* __restrict__ ol,
                      int R, int Cc, long long sIn, long long sOut)
{
    __shared__ float t[32][33];
    in += (long long)blockIdx.z * sIn;
    const long long ob = (long long)blockIdx.z * sOut;
    const int r0 = blockIdx.y * 32, c0 = blockIdx.x * 32;
    const int tx = threadIdx.x & 31, ty = threadIdx.x >> 5;
    #pragma unroll
    for (int i = 0; i < 32; i += 8)
        t[ty + i][tx] = in[(long long)(r0 + ty + i) * Cc + c0 + tx];
    __syncthreads();
    #pragma unroll
    for (int i = 0; i < 32; i += 8) {
        float v = t[tx][ty + i];
        float h = bf16_rn_f32(v);
        long long o = ob + (long long)(c0 + ty + i) * R + r0 + tx;
        oh[o] = __float2bfloat16(v);
        ol[o] = __float2bfloat16(v - h);
    }
}

// ---------------------------------------------------------------------------
extern "C" void kernel_launch(void* const* d_in, const int* in_sizes, int n_in,
                              void* d_out, int out_size)
{
    const float* x  = (const float*)d_in[0];
    const float* Wq = (const float*)d_in[1];
    const float* bq = (const float*)d_in[2];
    const float* Wk = (const float*)d_in[3];
    const float* bk = (const float*)d_in[4];
    const float* Wv = (const float*)d_in[5];
    const float* bv = (const float*)d_in[6];
    const float* Wo = (const float*)d_in[7];
    const float* bo = (const float*)d_in[8];
    float* out = (float*)d_out;

    const int M = NB * NSEQ;
    const float scale = 0.03125f;

    bf16 *xh, *xl, *wth, *wtl, *qh, *ql, *kh, *kl, *vth, *vtl, *ah, *al, *aoh, *aol;
    float *v, *P, *rinv;
    cudaGetSymbolAddress((void**)&xh,  g_xh);  cudaGetSymbolAddress((void**)&xl,  g_xl);
    cudaGetSymbolAddress((void**)&wth, g_wth); cudaGetSymbolAddress((void**)&wtl, g_wtl);
    cudaGetSymbolAddress((void**)&qh,  g_qh);  cudaGetSymbolAddress((void**)&ql,  g_ql);
    cudaGetSymbolAddress((void**)&kh,  g_kh);  cudaGetSymbolAddress((void**)&kl,  g_kl);
    cudaGetSymbolAddress((void**)&v,   g_v);
    cudaGetSymbolAddress((void**)&vth, g_vth); cudaGetSymbolAddress((void**)&vtl, g_vtl);
    cudaGetSymbolAddress((void**)&ah,  g_ah);  cudaGetSymbolAddress((void**)&al,  g_al);
    cudaGetSymbolAddress((void**)&aoh, g_aoh); cudaGetSymbolAddress((void**)&aol, g_aol);
    cudaGetSymbolAddress((void**)&P,   g_P);   cudaGetSymbolAddress((void**)&rinv, g_rinv);

    cudaFuncSetAttribute((const void*)tc_gemm7<0, true>,  cudaFuncAttributeMaxDynamicSharedMemorySize, SMEM_BYTES);
    cudaFuncSetAttribute((const void*)tc_gemm7<1, true>,  cudaFuncAttributeMaxDynamicSharedMemorySize, SMEM_BYTES);
    cudaFuncSetAttribute((const void*)tc_gemm7<2, false>, cudaFuncAttributeMaxDynamicSharedMemorySize, SMEM_BYTES);
    cudaFuncSetAttribute((const void*)tc_gemm7<3, false>, cudaFuncAttributeMaxDynamicSharedMemorySize, SMEM_BYTES);

    const long long qkv = (long long)NSEQ * DIMC;
    const long long ss  = (long long)NSEQ * NSEQ;

    dim3 b256(256);

    // 1) split x -> xh/xl
    conv_k<<<16384, b256>>>(x, xh, xl, 4194304);

    // 2) transpose+split weights
    {
        dim3 g(32, 32, 1);
        transpose_conv_k<<<g, b256>>>(Wq, wth + 0*1048576, wtl + 0*1048576, DIMC, DIMC, 0, 0);
        transpose_conv_k<<<g, b256>>>(Wk, wth + 1*1048576, wtl + 1*1048576, DIMC, DIMC, 0, 0);
        transpose_conv_k<<<g, b256>>>(Wv, wth + 2*1048576, wtl + 2*1048576, DIMC, DIMC, 0, 0);
        transpose_conv_k<<<g, b256>>>(Wo, wth + 3*1048576, wtl + 3*1048576, DIMC, DIMC, 0, 0);
    }

    // 3) q,k (bf16 pair out) and v (fp32 out) projections
    {
        dim3 g(M / 128, DIMC / BNC, 1);
        tc_gemm7<1, true><<<g, b256, SMEM_BYTES>>>(xh, xl, wth + 0*1048576, wtl + 0*1048576,
                                                   bq, nullptr, qh, ql, nullptr, nullptr, 0.f,
                                                   M, DIMC, DIMC, 0, 0, 0);
        tc_gemm7<1, true><<<g, b256, SMEM_BYTES>>>(xh, xl, wth + 1*1048576, wtl + 1*1048576,
                                                   bk, nullptr, kh, kl, nullptr, nullptr, 0.f,
                                                   M, DIMC, DIMC, 0, 0, 0);
        tc_gemm7<0, true><<<g, b256, SMEM_BYTES>>>(xh, xl, wth + 2*1048576, wtl + 2*1048576,
                                                   bv, v, nullptr, nullptr, nullptr, nullptr, 0.f,
                                                   M, DIMC, DIMC, 0, 0, 0);
    }

    // 4) vT split per batch
    {
        dim3 g(DIMC / 32, NSEQ / 32, NB);
        transpose_conv_k<<<g, b256>>>(v, vth, vtl, NSEQ, DIMC, qkv, qkv);
    }

    // 5) e = exp(scale * q@k^T)  -> ah/al (unnormalized) + row partials
    {
        dim3 g(NSEQ / 128, NSEQ / BNC, NB);
        tc_gemm7<2, false><<<g, b256, SMEM_BYTES>>>(qh, ql, kh, kl, nullptr,
                                                    nullptr, ah, al, nullptr, P, scale,
                                                    NSEQ, NSEQ, DIMC, qkv, qkv, ss);
    }

    // 6) rinv = 1/rowsum
    rowinv_k<<<64, b256>>>(P, rinv, NSEQ / BNC);

    // 7) ao = (e @ vT^T) * rinv  (bf16 pair out), K = 4096
    {
        dim3 g(NSEQ / 128, DIMC / BNC, NB);
        tc_gemm7<3, false><<<g, b256, SMEM_BYTES>>>(ah, al, vth, vtl, nullptr,
                                                    nullptr, aoh, aol, rinv, nullptr, 0.f,
                                                    NSEQ, DIMC, NSEQ, ss, qkv, qkv);
    }

    // 8) out = ao @ WoT^T + bo (fp32 out)
    {
        dim3 g(M / 128, DIMC / BNC, 1);
        tc_gemm7<0, true><<<g, b256, SMEM_BYTES>>>(aoh, aol, wth + 3*1048576, wtl + 3*1048576,
                                                   bo, out, nullptr, nullptr, nullptr, nullptr, 0.f,
                                                   M, DIMC, DIMC, 0, 0, 0);
    }
}